// round 15
// baseline (speedup 1.0000x reference)
#include <cuda_runtime.h>
#include <cuda_fp16.h>

#define BATCH 64
#define NIN   2048
#define DIN   16
#define NOUT  32
#define DOUT  32
#define JD    (NOUT*DOUT)   // 1024
#define STAGES 6            // cp.async ring depth per warp (4 warps * 6 * 2KB = 48KB)

// Scratch (device globals — no allocation allowed)
__device__ __half2 g_uhat[(size_t)BATCH * NIN * (JD/2)];  // [b][i][jd/2], 268 MB
__device__ float   g_s[BATCH * JD];
__device__ float   g_vsum[BATCH * JD];
__device__ int     g_cnt[3 * BATCH];    // completion counters (R0, route1, route2)

// ---------- packed f32x2 helpers (sm_103a) ----------
__device__ __forceinline__ unsigned long long pack2(float lo, float hi) {
    unsigned long long r;
    asm("mov.b64 %0, {%1, %2};" : "=l"(r) : "f"(lo), "f"(hi));
    return r;
}
__device__ __forceinline__ void unpack2(unsigned long long v, float& lo, float& hi) {
    asm("mov.b64 {%0, %1}, %2;" : "=f"(lo), "=f"(hi) : "l"(v));
}
__device__ __forceinline__ unsigned long long ffma2(unsigned long long a,
                                                    unsigned long long b,
                                                    unsigned long long c) {
    unsigned long long d;
    asm("fma.rn.f32x2 %0, %1, %2, %3;" : "=l"(d) : "l"(a), "l"(b), "l"(c));
    return d;
}
__device__ __forceinline__ unsigned long long fadd2(unsigned long long a,
                                                    unsigned long long b) {
    unsigned long long d;
    asm("add.rn.f32x2 %0, %1, %2;" : "=l"(d) : "l"(a), "l"(b));
    return d;
}
// Warp-wide f32 add via shuffle butterfly (redux.f32 not on sm_103).
__device__ __forceinline__ float warpAdd(float x) {
#pragma unroll
    for (int off = 16; off; off >>= 1) x += __shfl_xor_sync(0xffffffffu, x, off);
    return x;
}
__device__ __forceinline__ void cpAsync16(unsigned dst, const void* src) {
    asm volatile("cp.async.cg.shared.global [%0], [%1], 16;" :: "r"(dst), "l"(src));
}

// Squash for one batch b, executed by the LAST finishing block of a producer
// kernel. Reads g_s via .cg, computes v, accumulates g_vsum, zeroes g_s,
// optionally writes vout. Each warp pass covers exactly one j (32 d's).
__device__ __forceinline__ void squashTail(int b, float pre, int nthr,
                                           float* vout, bool writeOut) {
    for (int r = threadIdx.x; r < JD; r += nthr) {
        float s = __ldcg(&g_s[b * JD + r]) * pre;
        float s2 = warpAdd(s * s);
        float scale = (s2 / (1.f + s2 + 1e-9f)) * rsqrtf(s2 + 1e-9f);
        float v = s * scale;
        if (writeOut) vout[b * JD + r] = v;
        g_vsum[b * JD + r] += v;
        g_s[b * JD + r] = 0.f;
    }
}

// u_hat[b,i,jd] = sum_k W[i,jd,k] * x[b,i,k]; store fp16 (streaming stores).
// One block per i. Thread t owns jd pair (2t, 2t+1); W rows packed {w0,w1}
// per k. x staged as plain float4, read with warp-broadcast LDS.128.
// Also fuses the scratch zeroing (blocks 0..64).   [R12-proven inner loop]
__global__ void __launch_bounds__(512) kernelU(const float* __restrict__ x,
                                               const float* __restrict__ W) {
    __shared__ float4 xs[BATCH * 4];     // [b][quarter], 4 KB
    const int i = blockIdx.x;
    const int t = threadIdx.x;

    if (i < BATCH) {
        g_s[i * JD + t]       = 0.f;
        g_s[i * JD + 512 + t] = 0.f;
        g_vsum[i * JD + t]       = 0.f;
        g_vsum[i * JD + 512 + t] = 0.f;
    } else if (i == BATCH && t < 3 * BATCH) {
        g_cnt[t] = 0;
    }

    if (t < BATCH * 4) {
        int b = t >> 2, q = t & 3;
        xs[t] = reinterpret_cast<const float4*>(
                    x + (size_t)b * (NIN * DIN) + (size_t)i * DIN)[q];
    }

    const float4* W4 = reinterpret_cast<const float4*>(W + (size_t)i * JD * DIN);
    unsigned long long w2[DIN];
#pragma unroll
    for (int q = 0; q < 4; q++) {
        float4 fa = W4[8 * t + q];
        float4 fb = W4[8 * t + 4 + q];
        w2[4*q+0] = pack2(fa.x, fb.x);
        w2[4*q+1] = pack2(fa.y, fb.y);
        w2[4*q+2] = pack2(fa.z, fb.z);
        w2[4*q+3] = pack2(fa.w, fb.w);
    }
    __syncthreads();

    __half2* outp = g_uhat + (size_t)i * (JD/2) + t;
#pragma unroll 4
    for (int b = 0; b < BATCH; b++) {
        const float4* xb = xs + b * 4;
        unsigned long long accA = 0ull, accB = 0ull;
#pragma unroll
        for (int q = 0; q < 4; q++) {
            float4 f = xb[q];             // broadcast LDS.128
            accA = ffma2(w2[4*q + 0], pack2(f.x, f.x), accA);
            accB = ffma2(w2[4*q + 1], pack2(f.y, f.y), accB);
            accA = ffma2(w2[4*q + 2], pack2(f.z, f.z), accA);
            accB = ffma2(w2[4*q + 3], pack2(f.w, f.w), accB);
        }
        unsigned long long acc = fadd2(accA, accB);
        float a0, a1;
        unpack2(acc, a0, a1);
        __stcs(outp + (size_t)b * NIN * (JD/2), __floats2half2_rn(a0, a1));
    }
}

// Iter-0: s0[b,jd] = sum_i u_hat[b,i,jd]; last block per b also squashes.
__global__ void __launch_bounds__(256) kernelR0() {
    const int b = blockIdx.x;
    const int chunk = blockIdx.y;         // 16 chunks of 128 i's
    const int t = threadIdx.x;            // owns half2 pair -> jd 4t..4t+3
    float a0 = 0.f, a1 = 0.f, a2 = 0.f, a3 = 0.f;
    const uint2* base = reinterpret_cast<const uint2*>(
        g_uhat + ((size_t)b * NIN + (size_t)chunk * 128) * (JD/2)) + t;
#pragma unroll 8
    for (int ii = 0; ii < 128; ii++) {
        uint2 u = __ldcs(base + (size_t)ii * 256);   // streaming: 256 uint2 = one row
        float2 f0 = __half22float2(*reinterpret_cast<__half2*>(&u.x));
        float2 f1 = __half22float2(*reinterpret_cast<__half2*>(&u.y));
        a0 += f0.x; a1 += f0.y; a2 += f1.x; a3 += f1.y;
    }
    atomicAdd(&g_s[b * JD + 4*t + 0], a0);
    atomicAdd(&g_s[b * JD + 4*t + 1], a1);
    atomicAdd(&g_s[b * JD + 4*t + 2], a2);
    atomicAdd(&g_s[b * JD + 4*t + 3], a3);

    __threadfence();
    __syncthreads();
    __shared__ int done;
    if (t == 0) done = atomicAdd(&g_cnt[0 * BATCH + b], 1);
    __syncthreads();
    if (done == 15) {
        __threadfence();
        squashTail(b, 1.f / 32.f, 256, nullptr, false);
    }
}

// Routing iter (k>=1) with cp.async smem ring (6 stages x 2KB per warp = 48KB/block).
// Thread t owns chunks c = t+32k (k=0..3): capsule j = t/4 + 8k, d-range
// (t%4)*8..+8. Each thread copies and consumes ITS OWN chunks -> linear
// cp.async, conflict-free LDS.128, wait_group is the only sync in the loop.
// Softmax: quad-reduce (xor 1,2) for logits, xor 4,8,16 for the denominator;
// no max-subtraction (|l| <~ 10). Ring smem reused as reduction buffer + done flag.
// Grid 64x8 (512 blocks = single wave at 4 blocks/SM); warp does 64 rows.
__global__ void __launch_bounds__(128) kernelRoute(int cntRow,
                                                   float* __restrict__ vout,
                                                   int writeOut) {
    const int b = blockIdx.x;
    const int chunk = blockIdx.y;         // 8 chunks of 256 i's; warp does 64
    const int w = threadIdx.x >> 5;       // warp 0..3
    const int t = threadIdx.x & 31;       // lane

    __shared__ __align__(16) char smem_raw[4 * STAGES * 2048];   // 48 KB exactly
    uint4* ring = reinterpret_cast<uint4*>(smem_raw) + w * (STAGES * 128);

    const int m  = t >> 2;                // quad id: base capsule
    const int d0 = (t & 3) * 8;           // d offset within capsule

    float v[4][8];
#pragma unroll
    for (int k = 0; k < 4; k++) {
        const float4* vp = reinterpret_cast<const float4*>(
            g_vsum + b * JD + (m + 8 * k) * DOUT + d0);
        float4 f0 = vp[0], f1 = vp[1];
        v[k][0]=f0.x; v[k][1]=f0.y; v[k][2]=f0.z; v[k][3]=f0.w;
        v[k][4]=f1.x; v[k][5]=f1.y; v[k][6]=f1.z; v[k][7]=f1.w;
    }

    float acc[4][8];
#pragma unroll
    for (int k = 0; k < 4; k++)
#pragma unroll
        for (int r = 0; r < 8; r++) acc[k][r] = 0.f;

    const char* gsrc = reinterpret_cast<const char*>(
        g_uhat + ((size_t)b * NIN + chunk * 256 + w * 64) * (JD/2));

    unsigned ringAddr = (unsigned)__cvta_generic_to_shared(ring);

    // prologue: issue STAGES-1 = 5 rows
#pragma unroll
    for (int s = 0; s < STAGES - 1; s++) {
#pragma unroll
        for (int k = 0; k < 4; k++) {
            int c = t + 32 * k;
            cpAsync16(ringAddr + (s * 128 + c) * 16, gsrc + (size_t)s * 2048 + c * 16);
        }
        asm volatile("cp.async.commit_group;");
    }

    int cs = 0;               // consume stage = ii % STAGES
    int ps = STAGES - 1;      // produce stage = (ii + STAGES-1) % STAGES
#pragma unroll 1
    for (int ii = 0; ii < 64; ii++) {
        asm volatile("cp.async.wait_group %0;" :: "n"(STAGES - 2));
        const uint4* row = ring + cs * 128;

        float l[4];
#pragma unroll
        for (int k = 0; k < 4; k++) {
            uint4 uq = row[t + 32 * k];
            float2 f0 = __half22float2(*reinterpret_cast<const __half2*>(&uq.x));
            float2 f1 = __half22float2(*reinterpret_cast<const __half2*>(&uq.y));
            float2 f2 = __half22float2(*reinterpret_cast<const __half2*>(&uq.z));
            float2 f3 = __half22float2(*reinterpret_cast<const __half2*>(&uq.w));
            float pA = f0.x * v[k][0] + f1.x * v[k][2];
            float pB = f0.y * v[k][1] + f1.y * v[k][3];
            pA = fmaf(f2.x, v[k][4], pA); pB = fmaf(f2.y, v[k][5], pB);
            pA = fmaf(f3.x, v[k][6], pA); pB = fmaf(f3.y, v[k][7], pB);
            l[k] = pA + pB;
        }
#pragma unroll
        for (int k = 0; k < 4; k++) {
            l[k] += __shfl_xor_sync(0xffffffffu, l[k], 1);
            l[k] += __shfl_xor_sync(0xffffffffu, l[k], 2);
        }
        float e0 = __expf(l[0]), e1 = __expf(l[1]);
        float e2 = __expf(l[2]), e3 = __expf(l[3]);
        float sl = (e0 + e1) + (e2 + e3);
        sl += __shfl_xor_sync(0xffffffffu, sl, 4);
        sl += __shfl_xor_sync(0xffffffffu, sl, 8);
        sl += __shfl_xor_sync(0xffffffffu, sl, 16);
        float inv = __fdividef(1.f, sl);
        float ck[4] = {e0 * inv, e1 * inv, e2 * inv, e3 * inv};

#pragma unroll
        for (int k = 0; k < 4; k++) {
            uint4 uq = row[t + 32 * k];
            float2 f0 = __half22float2(*reinterpret_cast<const __half2*>(&uq.x));
            float2 f1 = __half22float2(*reinterpret_cast<const __half2*>(&uq.y));
            float2 f2 = __half22float2(*reinterpret_cast<const __half2*>(&uq.z));
            float2 f3 = __half22float2(*reinterpret_cast<const __half2*>(&uq.w));
            acc[k][0] = fmaf(ck[k], f0.x, acc[k][0]);
            acc[k][1] = fmaf(ck[k], f0.y, acc[k][1]);
            acc[k][2] = fmaf(ck[k], f1.x, acc[k][2]);
            acc[k][3] = fmaf(ck[k], f1.y, acc[k][3]);
            acc[k][4] = fmaf(ck[k], f2.x, acc[k][4]);
            acc[k][5] = fmaf(ck[k], f2.y, acc[k][5]);
            acc[k][6] = fmaf(ck[k], f3.x, acc[k][6]);
            acc[k][7] = fmaf(ck[k], f3.y, acc[k][7]);
        }

        int nr = ii + STAGES - 1;
        if (nr < 64) {
#pragma unroll
            for (int k = 0; k < 4; k++) {
                int c = t + 32 * k;
                cpAsync16(ringAddr + (ps * 128 + c) * 16, gsrc + (size_t)nr * 2048 + c * 16);
            }
        }
        asm volatile("cp.async.commit_group;");

        cs = (cs == STAGES - 1) ? 0 : cs + 1;
        ps = (ps == STAGES - 1) ? 0 : ps + 1;
    }

    asm volatile("cp.async.wait_group 0;");
    __syncthreads();

    // reuse ring smem: [0,16KB) per-warp reduction buffer, [16KB] done flag
    float* sred = reinterpret_cast<float*>(smem_raw);
    int*   doneP = reinterpret_cast<int*>(smem_raw + 4 * JD * sizeof(float));
#pragma unroll
    for (int k = 0; k < 4; k++) {
        int c = t + 32 * k;
#pragma unroll
        for (int r = 0; r < 8; r++) sred[w * JD + 8 * c + r] = acc[k][r];
    }
    __syncthreads();

    for (int r = threadIdx.x; r < JD; r += 128) {
        float sum = sred[0 * JD + r] + sred[1 * JD + r]
                  + sred[2 * JD + r] + sred[3 * JD + r];
        atomicAdd(&g_s[b * JD + r], sum);
    }

    __threadfence();
    __syncthreads();
    if (threadIdx.x == 0) *doneP = atomicAdd(&g_cnt[cntRow * BATCH + b], 1);
    __syncthreads();
    if (*doneP == 7) {
        __threadfence();
        squashTail(b, 1.f, 128, vout, writeOut != 0);
    }
}

extern "C" void kernel_launch(void* const* d_in, const int* in_sizes, int n_in,
                              void* d_out, int out_size) {
    const float* x = (const float*)d_in[0];   // [64, 2048, 16]
    const float* W = (const float*)d_in[1];   // [1, 2048, 32, 32, 16]
    float* out = (float*)d_out;               // [64, 32, 32]

    kernelU<<<2048, 512>>>(x, W);                      // + fused zeroing
    kernelR0<<<dim3(64, 16), 256>>>();                 // + squash iter 0
    kernelRoute<<<dim3(64, 8), 128>>>(1, out, 0);      // + squash iter 1
    kernelRoute<<<dim3(64, 8), 128>>>(2, out, 1);      // + squash iter 2 -> d_out
}

// round 16
// speedup vs baseline: 1.0875x; 1.0875x over previous
#include <cuda_runtime.h>
#include <cuda_fp16.h>

#define BATCH 64
#define NIN   2048
#define DIN   16
#define NOUT  32
#define DOUT  32
#define JD    (NOUT*DOUT)   // 1024
#define STAGES 4            // cp.async ring depth per warp

// Scratch (device globals — no allocation allowed)
__device__ __half2 g_uhat[(size_t)BATCH * NIN * (JD/2)];  // [b][i][jd/2], 268 MB
__device__ float   g_s[BATCH * JD];
__device__ float   g_vsum[BATCH * JD];
__device__ int     g_cnt[3 * BATCH];    // completion counters (R0, route1, route2)

// ---------- packed f32x2 helpers (sm_103a) ----------
__device__ __forceinline__ unsigned long long pack2(float lo, float hi) {
    unsigned long long r;
    asm("mov.b64 %0, {%1, %2};" : "=l"(r) : "f"(lo), "f"(hi));
    return r;
}
__device__ __forceinline__ void unpack2(unsigned long long v, float& lo, float& hi) {
    asm("mov.b64 {%0, %1}, %2;" : "=f"(lo), "=f"(hi) : "l"(v));
}
__device__ __forceinline__ unsigned long long ffma2(unsigned long long a,
                                                    unsigned long long b,
                                                    unsigned long long c) {
    unsigned long long d;
    asm("fma.rn.f32x2 %0, %1, %2, %3;" : "=l"(d) : "l"(a), "l"(b), "l"(c));
    return d;
}
__device__ __forceinline__ unsigned long long fadd2(unsigned long long a,
                                                    unsigned long long b) {
    unsigned long long d;
    asm("add.rn.f32x2 %0, %1, %2;" : "=l"(d) : "l"(a), "l"(b));
    return d;
}
// Warp-wide f32 add via shuffle butterfly (redux.f32 not on sm_103).
__device__ __forceinline__ float warpAdd(float x) {
#pragma unroll
    for (int off = 16; off; off >>= 1) x += __shfl_xor_sync(0xffffffffu, x, off);
    return x;
}
__device__ __forceinline__ void cpAsync16(unsigned dst, const void* src) {
    asm volatile("cp.async.cg.shared.global [%0], [%1], 16;" :: "r"(dst), "l"(src));
}

// Squash for one batch b, executed by the LAST finishing block of a producer
// kernel. Reads g_s via .cg, computes v, accumulates g_vsum, zeroes g_s,
// optionally writes vout. Each warp pass covers exactly one j (32 d's).
__device__ __forceinline__ void squashTail(int b, float pre, int nthr,
                                           float* vout, bool writeOut) {
    for (int r = threadIdx.x; r < JD; r += nthr) {
        float s = __ldcg(&g_s[b * JD + r]) * pre;
        float s2 = warpAdd(s * s);
        float scale = (s2 / (1.f + s2 + 1e-9f)) * rsqrtf(s2 + 1e-9f);
        float v = s * scale;
        if (writeOut) vout[b * JD + r] = v;
        g_vsum[b * JD + r] += v;
        g_s[b * JD + r] = 0.f;
    }
}

// u_hat[b,i,jd] = sum_k W[i,jd,k] * x[b,i,k]; store fp16.
// One block per i, 256 threads. Thread t owns jd QUAD (4t..4t+3): the 16
// per-b pack2 movs are amortized over 32 FFMA2 (vs 16), cutting issue slots
// per output from ~40 to ~28. x staged as plain float4, warp-broadcast
// LDS.128 (R12-proven). Fuses scratch zeroing (blocks 0..64).
__global__ void __launch_bounds__(256) kernelU(const float* __restrict__ x,
                                               const float* __restrict__ W) {
    __shared__ float4 xs[BATCH * 4];     // [b][quarter], 4 KB
    const int i = blockIdx.x;
    const int t = threadIdx.x;

    // fused zeroing (4 entries per thread)
    if (i < BATCH) {
#pragma unroll
        for (int q = 0; q < 4; q++) {
            g_s[i * JD + q * 256 + t]    = 0.f;
            g_vsum[i * JD + q * 256 + t] = 0.f;
        }
    } else if (i == BATCH && t < 3 * BATCH) {
        g_cnt[t] = 0;
    }

    // stage x[:, i, :] (256 float4 entries, one per thread)
    {
        int b = t >> 2, q = t & 3;
        xs[t] = reinterpret_cast<const float4*>(
                    x + (size_t)b * (NIN * DIN) + (size_t)i * DIN)[q];
    }

    // W rows 4t..4t+3 (16 floats each): wA packs rows (4t,4t+1), wB rows (4t+2,4t+3)
    const float4* W4 = reinterpret_cast<const float4*>(W + (size_t)i * JD * DIN);
    unsigned long long wA[DIN], wB[DIN];
#pragma unroll
    for (int q = 0; q < 4; q++) {
        float4 r0 = W4[(4 * t + 0) * 4 + q];
        float4 r1 = W4[(4 * t + 1) * 4 + q];
        float4 r2 = W4[(4 * t + 2) * 4 + q];
        float4 r3 = W4[(4 * t + 3) * 4 + q];
        wA[4*q+0] = pack2(r0.x, r1.x); wA[4*q+1] = pack2(r0.y, r1.y);
        wA[4*q+2] = pack2(r0.z, r1.z); wA[4*q+3] = pack2(r0.w, r1.w);
        wB[4*q+0] = pack2(r2.x, r3.x); wB[4*q+1] = pack2(r2.y, r3.y);
        wB[4*q+2] = pack2(r2.z, r3.z); wB[4*q+3] = pack2(r2.w, r3.w);
    }
    __syncthreads();

    // output: half2 pair (2t, 2t+1) per b -> one STG.64
    uint2* outp = reinterpret_cast<uint2*>(g_uhat + (size_t)i * (JD/2)) + t;
    const size_t bstr = (size_t)NIN * (JD/2) / 2;   // in uint2 units
#pragma unroll 2
    for (int b = 0; b < BATCH; b++) {
        const float4* xb = xs + b * 4;
        unsigned long long a0 = 0ull, a1 = 0ull;   // chains for jd (4t,4t+1)
        unsigned long long b0 = 0ull, b1 = 0ull;   // chains for jd (4t+2,4t+3)
#pragma unroll
        for (int q = 0; q < 4; q++) {
            float4 f = xb[q];             // broadcast LDS.128
            unsigned long long x0 = pack2(f.x, f.x);
            unsigned long long x1 = pack2(f.y, f.y);
            unsigned long long x2 = pack2(f.z, f.z);
            unsigned long long x3 = pack2(f.w, f.w);
            a0 = ffma2(wA[4*q+0], x0, a0);  b0 = ffma2(wB[4*q+0], x0, b0);
            a1 = ffma2(wA[4*q+1], x1, a1);  b1 = ffma2(wB[4*q+1], x1, b1);
            a0 = ffma2(wA[4*q+2], x2, a0);  b0 = ffma2(wB[4*q+2], x2, b0);
            a1 = ffma2(wA[4*q+3], x3, a1);  b1 = ffma2(wB[4*q+3], x3, b1);
        }
        unsigned long long accA = fadd2(a0, a1);
        unsigned long long accB = fadd2(b0, b1);
        float fa0, fa1, fb0, fb1;
        unpack2(accA, fa0, fa1);
        unpack2(accB, fb0, fb1);
        __half2 h0 = __floats2half2_rn(fa0, fa1);
        __half2 h1 = __floats2half2_rn(fb0, fb1);
        uint2 o;
        o.x = *reinterpret_cast<unsigned int*>(&h0);
        o.y = *reinterpret_cast<unsigned int*>(&h1);
        outp[(size_t)b * bstr] = o;
    }
}

// Iter-0: s0[b,jd] = sum_i u_hat[b,i,jd]; last block per b also squashes.
__global__ void __launch_bounds__(256) kernelR0() {
    const int b = blockIdx.x;
    const int chunk = blockIdx.y;         // 16 chunks of 128 i's
    const int t = threadIdx.x;            // owns half2 pair -> jd 4t..4t+3
    float a0 = 0.f, a1 = 0.f, a2 = 0.f, a3 = 0.f;
    const uint2* base = reinterpret_cast<const uint2*>(
        g_uhat + ((size_t)b * NIN + (size_t)chunk * 128) * (JD/2)) + t;
#pragma unroll 8
    for (int ii = 0; ii < 128; ii++) {
        uint2 u = __ldcg(base + (size_t)ii * 256);   // 256 uint2 = one row
        float2 f0 = __half22float2(*reinterpret_cast<__half2*>(&u.x));
        float2 f1 = __half22float2(*reinterpret_cast<__half2*>(&u.y));
        a0 += f0.x; a1 += f0.y; a2 += f1.x; a3 += f1.y;
    }
    atomicAdd(&g_s[b * JD + 4*t + 0], a0);
    atomicAdd(&g_s[b * JD + 4*t + 1], a1);
    atomicAdd(&g_s[b * JD + 4*t + 2], a2);
    atomicAdd(&g_s[b * JD + 4*t + 3], a3);

    __threadfence();
    __syncthreads();
    __shared__ int done;
    if (t == 0) done = atomicAdd(&g_cnt[0 * BATCH + b], 1);
    __syncthreads();
    if (done == 15) {
        __threadfence();
        squashTail(b, 1.f / 32.f, 256, nullptr, false);
    }
}

// Routing iter (k>=1) with cp.async smem ring (4 stages x 2KB per warp).
// [R14-proven form: grid 64x8, single wave]
__global__ void __launch_bounds__(128) kernelRoute(int cntRow,
                                                   float* __restrict__ vout,
                                                   int writeOut) {
    const int b = blockIdx.x;
    const int chunk = blockIdx.y;         // 8 chunks of 256 i's; warp does 64
    const int w = threadIdx.x >> 5;       // warp 0..3
    const int t = threadIdx.x & 31;       // lane

    __shared__ __align__(16) char smem_raw[4 * STAGES * 2048];   // 32 KB
    uint4* ring = reinterpret_cast<uint4*>(smem_raw) + w * (STAGES * 128);

    const int m  = t >> 2;                // quad id: base capsule
    const int d0 = (t & 3) * 8;           // d offset within capsule

    float v[4][8];
#pragma unroll
    for (int k = 0; k < 4; k++) {
        const float4* vp = reinterpret_cast<const float4*>(
            g_vsum + b * JD + (m + 8 * k) * DOUT + d0);
        float4 f0 = vp[0], f1 = vp[1];
        v[k][0]=f0.x; v[k][1]=f0.y; v[k][2]=f0.z; v[k][3]=f0.w;
        v[k][4]=f1.x; v[k][5]=f1.y; v[k][6]=f1.z; v[k][7]=f1.w;
    }

    float acc[4][8];
#pragma unroll
    for (int k = 0; k < 4; k++)
#pragma unroll
        for (int r = 0; r < 8; r++) acc[k][r] = 0.f;

    const char* gsrc = reinterpret_cast<const char*>(
        g_uhat + ((size_t)b * NIN + chunk * 256 + w * 64) * (JD/2));

    unsigned ringAddr = (unsigned)__cvta_generic_to_shared(ring);

#pragma unroll
    for (int s = 0; s < STAGES - 1; s++) {
#pragma unroll
        for (int k = 0; k < 4; k++) {
            int c = t + 32 * k;
            cpAsync16(ringAddr + (s * 128 + c) * 16, gsrc + (size_t)s * 2048 + c * 16);
        }
        asm volatile("cp.async.commit_group;");
    }

#pragma unroll 1
    for (int ii = 0; ii < 64; ii++) {
        asm volatile("cp.async.wait_group %0;" :: "n"(STAGES - 2));
        const uint4* row = ring + (ii & (STAGES - 1)) * 128;

        float l[4];
#pragma unroll
        for (int k = 0; k < 4; k++) {
            uint4 uq = row[t + 32 * k];
            float2 f0 = __half22float2(*reinterpret_cast<const __half2*>(&uq.x));
            float2 f1 = __half22float2(*reinterpret_cast<const __half2*>(&uq.y));
            float2 f2 = __half22float2(*reinterpret_cast<const __half2*>(&uq.z));
            float2 f3 = __half22float2(*reinterpret_cast<const __half2*>(&uq.w));
            float pA = f0.x * v[k][0] + f1.x * v[k][2];
            float pB = f0.y * v[k][1] + f1.y * v[k][3];
            pA = fmaf(f2.x, v[k][4], pA); pB = fmaf(f2.y, v[k][5], pB);
            pA = fmaf(f3.x, v[k][6], pA); pB = fmaf(f3.y, v[k][7], pB);
            l[k] = pA + pB;
        }
#pragma unroll
        for (int k = 0; k < 4; k++) {
            l[k] += __shfl_xor_sync(0xffffffffu, l[k], 1);
            l[k] += __shfl_xor_sync(0xffffffffu, l[k], 2);
        }
        float e0 = __expf(l[0]), e1 = __expf(l[1]);
        float e2 = __expf(l[2]), e3 = __expf(l[3]);
        float sl = (e0 + e1) + (e2 + e3);
        sl += __shfl_xor_sync(0xffffffffu, sl, 4);
        sl += __shfl_xor_sync(0xffffffffu, sl, 8);
        sl += __shfl_xor_sync(0xffffffffu, sl, 16);
        float inv = __fdividef(1.f, sl);
        float ck[4] = {e0 * inv, e1 * inv, e2 * inv, e3 * inv};

#pragma unroll
        for (int k = 0; k < 4; k++) {
            uint4 uq = row[t + 32 * k];
            float2 f0 = __half22float2(*reinterpret_cast<const __half2*>(&uq.x));
            float2 f1 = __half22float2(*reinterpret_cast<const __half2*>(&uq.y));
            float2 f2 = __half22float2(*reinterpret_cast<const __half2*>(&uq.z));
            float2 f3 = __half22float2(*reinterpret_cast<const __half2*>(&uq.w));
            acc[k][0] = fmaf(ck[k], f0.x, acc[k][0]);
            acc[k][1] = fmaf(ck[k], f0.y, acc[k][1]);
            acc[k][2] = fmaf(ck[k], f1.x, acc[k][2]);
            acc[k][3] = fmaf(ck[k], f1.y, acc[k][3]);
            acc[k][4] = fmaf(ck[k], f2.x, acc[k][4]);
            acc[k][5] = fmaf(ck[k], f2.y, acc[k][5]);
            acc[k][6] = fmaf(ck[k], f3.x, acc[k][6]);
            acc[k][7] = fmaf(ck[k], f3.y, acc[k][7]);
        }

        int nr = ii + STAGES - 1;
        if (nr < 64) {
            int s = nr & (STAGES - 1);
#pragma unroll
            for (int k = 0; k < 4; k++) {
                int c = t + 32 * k;
                cpAsync16(ringAddr + (s * 128 + c) * 16, gsrc + (size_t)nr * 2048 + c * 16);
            }
        }
        asm volatile("cp.async.commit_group;");
    }

    asm volatile("cp.async.wait_group 0;");
    __syncthreads();

    // reuse ring smem as per-warp reduction buffer: sred[w][jd], jd = 8c + r
    float* sred = reinterpret_cast<float*>(smem_raw);
#pragma unroll
    for (int k = 0; k < 4; k++) {
        int c = t + 32 * k;
#pragma unroll
        for (int r = 0; r < 8; r++) sred[w * JD + 8 * c + r] = acc[k][r];
    }
    __syncthreads();

    for (int r = threadIdx.x; r < JD; r += 128) {
        float sum = sred[0 * JD + r] + sred[1 * JD + r]
                  + sred[2 * JD + r] + sred[3 * JD + r];
        atomicAdd(&g_s[b * JD + r], sum);
    }

    __threadfence();
    __syncthreads();
    __shared__ int done;
    if (threadIdx.x == 0) done = atomicAdd(&g_cnt[cntRow * BATCH + b], 1);
    __syncthreads();
    if (done == 7) {
        __threadfence();
        squashTail(b, 1.f, 128, vout, writeOut != 0);
    }
}

extern "C" void kernel_launch(void* const* d_in, const int* in_sizes, int n_in,
                              void* d_out, int out_size) {
    const float* x = (const float*)d_in[0];   // [64, 2048, 16]
    const float* W = (const float*)d_in[1];   // [1, 2048, 32, 32, 16]
    float* out = (float*)d_out;               // [64, 32, 32]

    kernelU<<<2048, 256>>>(x, W);                      // + fused zeroing
    kernelR0<<<dim3(64, 16), 256>>>();                 // + squash iter 0
    kernelRoute<<<dim3(64, 8), 128>>>(1, out, 0);      // + squash iter 1
    kernelRoute<<<dim3(64, 8), 128>>>(2, out, 1);      // + squash iter 2 -> d_out
}